// round 13
// baseline (speedup 1.0000x reference)
#include <cuda_runtime.h>
#include <cuda_fp16.h>
#include <math.h>
#include <stdint.h>

#define N_NODES 10000
#define N_EDGES 80000
#define EMB_DIM 128
#define IN_CH 64
#define IN_GNN 191
#define K1PAD 192
#define C1 2048
#define C2 1024
#define C3 1024
#define NUM_GRAPHS 16
#define H3 512
#define NUM_CLASSES 2

// ---------------- scratch (device globals) ------------------------------------
__device__ __half d_h16[N_NODES * C1];           // GEMM output / y16 buffer
__device__ __half d_a16[N_NODES * C1];           // fp16 activations
__device__ __half d_wt1[C1 * K1PAD];             // W1^T fp16 [2048, 192]
__device__ __half d_wt2[C2 * C1];                // W2^T fp16 [1024, 2048]
__device__ __half d_wt3[C3 * C2];                // W3^T fp16 [1024, 1024]
__device__ float  d_dinv[N_NODES];
__device__ int    d_cnt[N_NODES];
__device__ int    d_rowptr[N_NODES + 1];
__device__ int    d_wofs[N_NODES];
__device__ int    d_colidx[N_EDGES];
__device__ float  d_eval[N_EDGES];
__device__ float  d_pool[NUM_GRAPHS * C3];
__device__ float  d_gcnt[NUM_GRAPHS];
__device__ float  d_m1[NUM_GRAPHS * 1024];
__device__ float  d_m2[NUM_GRAPHS * 1024];
__device__ float  d_m3[NUM_GRAPHS * H3];

// ---------------- helpers -------------------------------------------------------
__device__ __forceinline__ uint32_t smem_u32(const void* p) {
    uint32_t a;
    asm("{ .reg .u64 t; cvta.to.shared.u64 t, %1; cvt.u32.u64 %0, t; }"
        : "=r"(a) : "l"(p));
    return a;
}
__device__ __forceinline__ void cp16(uint32_t dst, const void* src, bool pred) {
    int sz = pred ? 16 : 0;
    asm volatile("cp.async.cg.shared.global [%0], [%1], 16, %2;"
                 :: "r"(dst), "l"(src), "r"(sz) : "memory");
}
#define CP_COMMIT() asm volatile("cp.async.commit_group;" ::: "memory")
#define CP_WAIT2()  asm volatile("cp.async.wait_group 2;" ::: "memory")

__device__ __forceinline__ void ldsm4(uint32_t (&r)[4], uint32_t a) {
    asm volatile("ldmatrix.sync.aligned.m8n8.x4.shared.b16 {%0,%1,%2,%3}, [%4];"
        : "=r"(r[0]), "=r"(r[1]), "=r"(r[2]), "=r"(r[3]) : "r"(a));
}
__device__ __forceinline__ void mma16816(float (&d)[4], const uint32_t (&a)[4],
                                         const uint32_t* b) {
    asm volatile("mma.sync.aligned.m16n8k16.row.col.f32.f16.f16.f32 "
        "{%0,%1,%2,%3}, {%4,%5,%6,%7}, {%8,%9}, {%0,%1,%2,%3};"
        : "+f"(d[0]), "+f"(d[1]), "+f"(d[2]), "+f"(d[3])
        : "r"(a[0]), "r"(a[1]), "r"(a[2]), "r"(a[3]), "r"(b[0]), "r"(b[1]));
}

// ---------------- setup kernels -------------------------------------------------
__global__ void init_kernel() {
    int i = blockIdx.x * blockDim.x + threadIdx.x;
    int total = N_NODES + NUM_GRAPHS * C3 + NUM_GRAPHS;
    for (; i < total; i += gridDim.x * blockDim.x) {
        if (i < N_NODES) d_cnt[i] = 0;
        else if (i < N_NODES + NUM_GRAPHS * C3) d_pool[i - N_NODES] = 0.0f;
        else d_gcnt[i - N_NODES - NUM_GRAPHS * C3] = 0.0f;
    }
}
__global__ void count_kernel(const int* __restrict__ ei,
                             const int* __restrict__ batch) {
    int idx = blockIdx.x * blockDim.x + threadIdx.x;
    if (idx < N_EDGES) atomicAdd(&d_cnt[ei[N_EDGES + idx]], 1);
    if (idx < N_NODES) atomicAdd(&d_gcnt[batch[idx]], 1.0f);
}
// fused: exclusive scan of counts + dinv (warp-shuffle scan, 2 barriers)
__global__ void scan_kernel() {
    __shared__ int wsum[32];
    const int CH = (N_NODES + 1023) / 1024;  // 10
    int tid = threadIdx.x, lane = tid & 31, wid = tid >> 5;
    int base = tid * CH, s = 0;
    for (int k = 0; k < CH; k++) { int i = base + k; if (i < N_NODES) s += d_cnt[i]; }
    int v = s;
    #pragma unroll
    for (int off = 1; off < 32; off <<= 1) {
        int t = __shfl_up_sync(0xffffffffu, v, off);
        if (lane >= off) v += t;
    }
    if (lane == 31) wsum[wid] = v;
    __syncthreads();
    if (wid == 0) {
        int w = wsum[lane];
        #pragma unroll
        for (int off = 1; off < 32; off <<= 1) {
            int t = __shfl_up_sync(0xffffffffu, w, off);
            if (lane >= off) w += t;
        }
        wsum[lane] = w;
    }
    __syncthreads();
    int run = (v - s) + (wid > 0 ? wsum[wid - 1] : 0);  // exclusive prefix
    for (int k = 0; k < CH; k++) {
        int i = base + k;
        if (i < N_NODES) {
            d_rowptr[i] = run; d_wofs[i] = run; run += d_cnt[i];
            d_dinv[i] = rsqrtf((float)(d_cnt[i] + 1));
        }
    }
    if (tid == 1023) d_rowptr[N_NODES] = run;
}
__global__ void fill_kernel(const int* __restrict__ ei) {
    int e = blockIdx.x * blockDim.x + threadIdx.x;
    if (e < N_EDGES) {
        int src = ei[e], dst = ei[N_EDGES + e];
        int pos = atomicAdd(&d_wofs[dst], 1);
        d_colidx[pos] = src;
        d_eval[pos] = d_dinv[src] * d_dinv[dst];
    }
}
// embed + concat straight to fp16 (padded to K1PAD)
__global__ void embed_kernel(const int* __restrict__ tids,
                             const float* __restrict__ other,
                             const float* __restrict__ emb) {
    int i = blockIdx.x, c = threadIdx.x;  // c in [0, K1PAD)
    float v = 0.0f;
    if (c < EMB_DIM) v = emb[tids[i] * EMB_DIM + c];
    else if (c < IN_GNN) v = other[i * (IN_CH - 1) + (c - EMB_DIM)];
    d_a16[i * K1PAD + c] = __float2half(v);
}

// fused transpose of W1, W2, W3 (grid.z selects matrix; early-exit off-range)
__global__ void tconv_all_kernel(const float* __restrict__ W1,
                                 const float* __restrict__ W2,
                                 const float* __restrict__ W3) {
    __shared__ float t[32][33];
    int z = blockIdx.z;
    const float* W; __half* dst; int Kin, Kpad, Nn;
    if (z == 0)      { W = W1; Kin = IN_GNN; Kpad = K1PAD; Nn = C1; dst = d_wt1; }
    else if (z == 1) { W = W2; Kin = C1;     Kpad = C1;    Nn = C2; dst = d_wt2; }
    else             { W = W3; Kin = C2;     Kpad = C2;    Nn = C3; dst = d_wt3; }
    int k0 = blockIdx.x * 32, n0 = blockIdx.y * 32;
    if (k0 >= Kpad || n0 >= Nn) return;
    int tx = threadIdx.x, ty = threadIdx.y;
    int k = k0 + ty, n = n0 + tx;
    t[ty][tx] = (k < Kin) ? W[(long)k * Nn + n] : 0.0f;
    __syncthreads();
    int nw = n0 + ty, kw = k0 + tx;
    dst[(long)nw * Kpad + kw] = __float2half(t[tx][ty]);
}

// ---------------- mma.sync fp16 GEMM (128x128, BK=64, 3 stages) ----------------
// Optional fused bias+ReLU epilogue (bias != nullptr).
#define BM 128
#define BN 128
#define BK 64
#define TILE_BYTES (128 * 64 * 2)      // 16 KB per tile
#define STAGE_BYTES (2 * TILE_BYTES)   // 32 KB (A, B)
#define NSTAGE 3

__global__ __launch_bounds__(256) void mma_gemm_kernel(
    const __half* __restrict__ A, const __half* __restrict__ B,
    __half* __restrict__ C16, const float* __restrict__ bias,
    int M, int Nn, int Kp) {
    extern __shared__ char smem[];
    uint32_t sbase = smem_u32(smem);
    int tid = threadIdx.x;
    int row0 = blockIdx.y * BM, col0 = blockIdx.x * BN;
    int nkt = Kp / BK;

    int w = tid >> 5, lane = tid & 31;
    int wm = (w & 3) * 32;   // 4 warps along M
    int wn = (w >> 2) * 64;  // 2 warps along N
    int q = lane >> 3, rr = lane & 7;

    float acc[2][8][4] = {};

    auto issue_stage = [&](int kt, int slot) {
        int k0 = kt * BK;
        #pragma unroll
        for (int i = 0; i < 8; i++) {
            int idx = tid + i * 256;
            int t = idx >> 10;           // 0 = A, 1 = B
            int r = (idx >> 3) & 127;
            int c = idx & 7;
            int grow = ((t == 0) ? row0 : col0) + r;
            bool ok = (t == 1) || (grow < M);
            const __half* s = (t == 0) ? A : B;
            const char* gp = (const char*)(s + (size_t)(ok ? grow : 0) * Kp + k0) + c * 16;
            uint32_t so = sbase + slot * STAGE_BYTES + t * TILE_BYTES
                        + r * 128 + ((c ^ (r & 7)) << 4);
            cp16(so, gp, ok);
        }
        CP_COMMIT();
    };

    #pragma unroll
    for (int s = 0; s < NSTAGE; s++) {
        if (s < nkt) issue_stage(s, s); else CP_COMMIT();
    }

    int st = 0;
    for (int kt = 0; kt < nkt; kt++) {
        CP_WAIT2();
        __syncthreads();
        uint32_t abase = sbase + st * STAGE_BYTES;
        uint32_t bbase = abase + TILE_BYTES;
        #pragma unroll
        for (int ks = 0; ks < 4; ks++) {
            uint32_t ah[2][4];
            #pragma unroll
            for (int mf = 0; mf < 2; mf++) {
                int row = wm + mf * 16 + (q & 1) * 8 + rr;
                int c = 2 * ks + (q >> 1);
                uint32_t off = row * 128 + ((c ^ (row & 7)) << 4);
                ldsm4(ah[mf], abase + off);
            }
            uint32_t bfr[8][2];
            #pragma unroll
            for (int nf2 = 0; nf2 < 4; nf2++) {
                int n = wn + nf2 * 16 + (q >> 1) * 8 + rr;
                int c = 2 * ks + (q & 1);
                uint32_t off = n * 128 + ((c ^ (n & 7)) << 4);
                uint32_t t0[4];
                ldsm4(t0, bbase + off);
                bfr[2*nf2][0] = t0[0]; bfr[2*nf2][1] = t0[1];
                bfr[2*nf2+1][0] = t0[2]; bfr[2*nf2+1][1] = t0[3];
            }
            #pragma unroll
            for (int mf = 0; mf < 2; mf++)
                #pragma unroll
                for (int nf = 0; nf < 8; nf++)
                    mma16816(acc[mf][nf], ah[mf], bfr[nf]);
        }
        __syncthreads();
        if (kt + NSTAGE < nkt) issue_stage(kt + NSTAGE, st);
        else CP_COMMIT();
        st = (st == NSTAGE - 1) ? 0 : st + 1;
    }

    // epilogue: fp16 output, optional fused bias+ReLU
    #pragma unroll
    for (int mf = 0; mf < 2; mf++) {
        int r0 = row0 + wm + mf * 16 + (lane >> 2);
        #pragma unroll
        for (int nf = 0; nf < 8; nf++) {
            int cc = col0 + wn + nf * 8 + (lane & 3) * 2;
            float v0 = acc[mf][nf][0], v1 = acc[mf][nf][1];
            float v2 = acc[mf][nf][2], v3 = acc[mf][nf][3];
            if (bias) {
                float bx = __ldg(bias + cc), by = __ldg(bias + cc + 1);
                v0 = fmaxf(v0 + bx, 0.0f); v1 = fmaxf(v1 + by, 0.0f);
                v2 = fmaxf(v2 + bx, 0.0f); v3 = fmaxf(v3 + by, 0.0f);
            }
            if (r0 < M)
                *(__half2*)(C16 + (size_t)r0 * Nn + cc) = __floats2half2_rn(v0, v1);
            if (r0 + 8 < M)
                *(__half2*)(C16 + (size_t)(r0 + 8) * Nn + cc) = __floats2half2_rn(v2, v3);
        }
    }
}

// ------ common 4-channel gather body --------------------------------------------
__device__ __forceinline__ void acc4(float (&a)[4], float wv, uint2 v) {
    __half2 lo = *(__half2*)&v.x, hi = *(__half2*)&v.y;
    float2 f0 = __half22float2(lo), f1 = __half22float2(hi);
    a[0] = fmaf(wv, f0.x, a[0]); a[1] = fmaf(wv, f0.y, a[1]);
    a[2] = fmaf(wv, f1.x, a[2]); a[3] = fmaf(wv, f1.y, a[3]);
}
__device__ __forceinline__ void gather_row(float (&a)[4], const uint2* h4,
                                           int i, int nc4, int c4) {
    float di = d_dinv[i];
    acc4(a, di * di, h4[(size_t)i * nc4 + c4]);
    int e0 = d_rowptr[i], e1 = d_rowptr[i + 1];
    int e = e0;
    for (; e + 4 <= e1; e += 4) {
        int   i0 = d_colidx[e],     i1 = d_colidx[e + 1];
        int   i2 = d_colidx[e + 2], i3 = d_colidx[e + 3];
        float w0e = d_eval[e],      w1e = d_eval[e + 1];
        float w2e = d_eval[e + 2],  w3e = d_eval[e + 3];
        uint2 v0 = h4[(size_t)i0 * nc4 + c4];
        uint2 v1 = h4[(size_t)i1 * nc4 + c4];
        uint2 v2 = h4[(size_t)i2 * nc4 + c4];
        uint2 v3 = h4[(size_t)i3 * nc4 + c4];
        acc4(a, w0e, v0); acc4(a, w1e, v1); acc4(a, w2e, v2); acc4(a, w3e, v3);
    }
    for (; e < e1; e++)
        acc4(a, d_eval[e], h4[(size_t)d_colidx[e] * nc4 + c4]);
}

// ------ SpMM + bias + ReLU (layers 2, 3) ----------------------------------------
__global__ void spmm_relu_kernel(const __half* __restrict__ h16,
                                 const float* __restrict__ bias,
                                 __half* __restrict__ out16, int Cch) {
    int i = blockIdx.x;
    int c4 = blockIdx.y * blockDim.x + threadIdx.x;
    int nc4 = Cch >> 2;
    if (c4 >= nc4) return;
    float a[4] = {0.f, 0.f, 0.f, 0.f};
    gather_row(a, (const uint2*)h16, i, nc4, c4);
    const float4 bv = *(const float4*)(bias + 4 * c4);
    a[0] += bv.x; a[1] += bv.y; a[2] += bv.z; a[3] += bv.w;
    #pragma unroll
    for (int t = 0; t < 4; t++) a[t] = a[t] > 0.0f ? a[t] : 0.0f;
    uint2 o;
    *(__half2*)&o.x = __floats2half2_rn(a[0], a[1]);
    *(__half2*)&o.y = __floats2half2_rn(a[2], a[3]);
    ((uint2*)out16)[(size_t)i * nc4 + c4] = o;
}

// ------ plain aggregate SpMM for narrow layer-1 input (no bias/relu) ------------
#define NPB 5
__global__ void spmm_agg_kernel(const __half* __restrict__ x16,
                                __half* __restrict__ y16) {
    const int nc4 = K1PAD >> 2;  // 48
    int c4 = threadIdx.x;
    int i = blockIdx.x * NPB + threadIdx.y;
    if (c4 >= nc4 || i >= N_NODES) return;
    float a[4] = {0.f, 0.f, 0.f, 0.f};
    gather_row(a, (const uint2*)x16, i, nc4, c4);
    uint2 o;
    *(__half2*)&o.x = __floats2half2_rn(a[0], a[1]);
    *(__half2*)&o.y = __floats2half2_rn(a[2], a[3]);
    ((uint2*)y16)[(size_t)i * nc4 + c4] = o;
}

// ---------------- pooling (reads fp16 activations) -----------------------------
#define POOL_CHUNK 64
__global__ void pool_kernel(const __half* __restrict__ h16,
                            const int* __restrict__ batch) {
    int c = blockIdx.y * blockDim.x + threadIdx.x;   // channel
    int i0 = blockIdx.x * POOL_CHUNK;
    int iend = min(i0 + POOL_CHUNK, N_NODES);
    if (i0 >= N_NODES) return;
    float acc = 0.0f;
    int cur = batch[i0];
    for (int i = i0; i < iend; i++) {
        int b = batch[i];
        if (b != cur) { atomicAdd(&d_pool[cur * C3 + c], acc); acc = 0.0f; cur = b; }
        acc += __half2float(h16[(size_t)i * C3 + c]);
    }
    atomicAdd(&d_pool[cur * C3 + c], acc);
}

// ------- small MLP (unroll-4 accumulators; optional mean-divide on input) -------
__global__ void mlp_kernel(const float* __restrict__ in,
                           const float* __restrict__ W,
                           const float* __restrict__ bias,
                           float* __restrict__ out,
                           int K, int Mo, int do_relu, int do_mean) {
    __shared__ float sin[1024];
    int row = blockIdx.y;
    float scale = 1.0f;
    if (do_mean) scale = 1.0f / fmaxf(d_gcnt[row], 1.0f);
    for (int k = threadIdx.x; k < K; k += blockDim.x)
        sin[k] = in[row * K + k] * scale;
    __syncthreads();
    int col = blockIdx.x * blockDim.x + threadIdx.x;
    if (col < Mo) {
        float a0 = 0.f, a1 = 0.f, a2 = 0.f, a3 = 0.f;
        for (int k = 0; k < K; k += 4) {
            a0 = fmaf(sin[k],     W[(k)     * Mo + col], a0);
            a1 = fmaf(sin[k + 1], W[(k + 1) * Mo + col], a1);
            a2 = fmaf(sin[k + 2], W[(k + 2) * Mo + col], a2);
            a3 = fmaf(sin[k + 3], W[(k + 3) * Mo + col], a3);
        }
        float acc = bias[col] + (a0 + a1) + (a2 + a3);
        if (do_relu) acc = acc > 0.0f ? acc : 0.0f;
        out[row * Mo + col] = acc;
    }
}

// ---------------- launch --------------------------------------------------------
extern "C" void kernel_launch(void* const* d_in, const int* in_sizes, int n_in,
                              void* d_out, int out_size) {
    const int*   type_ids = (const int*)  d_in[0];
    const float* other    = (const float*)d_in[1];
    const int*   eidx     = (const int*)  d_in[2];
    const int*   batch    = (const int*)  d_in[3];
    const float* emb      = (const float*)d_in[4];
    const float* W1 = (const float*)d_in[5];  const float* b1 = (const float*)d_in[6];
    const float* W2 = (const float*)d_in[7];  const float* b2 = (const float*)d_in[8];
    const float* W3 = (const float*)d_in[9];  const float* b3 = (const float*)d_in[10];
    const float* h1w = (const float*)d_in[11]; const float* h1b = (const float*)d_in[12];
    const float* h2w = (const float*)d_in[13]; const float* h2b = (const float*)d_in[14];
    const float* h3w = (const float*)d_in[15]; const float* h3b = (const float*)d_in[16];
    const float* ow  = (const float*)d_in[17]; const float* ob  = (const float*)d_in[18];
    float* out = (float*)d_out;

    float* pool_p; cudaGetSymbolAddress((void**)&pool_p, d_pool);
    float* m1_p;   cudaGetSymbolAddress((void**)&m1_p,  d_m1);
    float* m2_p;   cudaGetSymbolAddress((void**)&m2_p,  d_m2);
    float* m3_p;   cudaGetSymbolAddress((void**)&m3_p,  d_m3);
    __half* h16_p; cudaGetSymbolAddress((void**)&h16_p, d_h16);
    __half* a16_p; cudaGetSymbolAddress((void**)&a16_p, d_a16);
    __half* wt1_p; cudaGetSymbolAddress((void**)&wt1_p, d_wt1);
    __half* wt2_p; cudaGetSymbolAddress((void**)&wt2_p, d_wt2);
    __half* wt3_p; cudaGetSymbolAddress((void**)&wt3_p, d_wt3);

    static int smem_set = 0;
    if (!smem_set) {
        cudaFuncSetAttribute(mma_gemm_kernel,
                             cudaFuncAttributeMaxDynamicSharedMemorySize,
                             NSTAGE * STAGE_BYTES);
        smem_set = 1;
    }

    // graph structure + all weight transposes (one launch)
    init_kernel<<<128, 256>>>();
    count_kernel<<<(N_EDGES + 255) / 256, 256>>>(eidx, batch);
    tconv_all_kernel<<<dim3(C1 / 32, C1 / 32, 3), dim3(32, 32)>>>(W1, W2, W3);
    scan_kernel<<<1, 1024>>>();
    fill_kernel<<<(N_EDGES + 255) / 256, 256>>>(eidx);
    embed_kernel<<<N_NODES, K1PAD>>>(type_ids, other, emb);

    const int MT = (N_NODES + BM - 1) / BM;  // 79

    // --- layer 1 (reordered): y = agg(x) [N,192]; a = relu(y@W1t + b1) ----------
    {
        dim3 ag((N_NODES + NPB - 1) / NPB);
        spmm_agg_kernel<<<ag, dim3(K1PAD / 4, NPB)>>>(a16_p, h16_p);
        dim3 grid(C1 / BN, MT);
        mma_gemm_kernel<<<grid, 256, NSTAGE * STAGE_BYTES>>>(h16_p, wt1_p, a16_p, b1,
                                                             N_NODES, C1, K1PAD);
    }
    // --- layer 2: h = a@W2t; a = relu(agg(h) + b2) -------------------------------
    {
        dim3 grid(C2 / BN, MT);
        mma_gemm_kernel<<<grid, 256, NSTAGE * STAGE_BYTES>>>(a16_p, wt2_p, h16_p,
                                                             nullptr, N_NODES, C2, C1);
        dim3 sg(N_NODES, (C2 / 4) / 256);
        spmm_relu_kernel<<<sg, 256>>>(h16_p, b2, a16_p, C2);
    }
    // --- layer 3: h = a@W3t; a = relu(agg(h) + b3) -------------------------------
    {
        dim3 grid(C3 / BN, MT);
        mma_gemm_kernel<<<grid, 256, NSTAGE * STAGE_BYTES>>>(a16_p, wt3_p, h16_p,
                                                             nullptr, N_NODES, C3, C2);
        dim3 sg(N_NODES, (C3 / 4) / 256);
        spmm_relu_kernel<<<sg, 256>>>(h16_p, b3, a16_p, C3);
    }

    // pool + head (mean folded into first MLP layer)
    {
        dim3 grid((N_NODES + POOL_CHUNK - 1) / POOL_CHUNK, C3 / 256);
        pool_kernel<<<grid, 256>>>(a16_p, batch);
        dim3 g1(1024 / 256, NUM_GRAPHS);
        mlp_kernel<<<g1, 256>>>(pool_p, h1w, h1b, m1_p, 1024, 1024, 1, 1);
        mlp_kernel<<<g1, 256>>>(m1_p, h2w, h2b, m2_p, 1024, 1024, 1, 0);
        dim3 g3(H3 / 256, NUM_GRAPHS);
        mlp_kernel<<<g3, 256>>>(m2_p, h3w, h3b, m3_p, 1024, H3, 1, 0);
        dim3 g4(1, NUM_GRAPHS);
        mlp_kernel<<<g4, 256>>>(m3_p, ow, ob, out, H3, NUM_CLASSES, 0, 0);
    }
}

// round 14
// speedup vs baseline: 1.1474x; 1.1474x over previous
#include <cuda_runtime.h>
#include <cuda_fp16.h>
#include <math.h>
#include <stdint.h>

#define N_NODES 10000
#define N_EDGES 80000
#define EMB_DIM 128
#define IN_CH 64
#define IN_GNN 191
#define K1PAD 192
#define C1 2048
#define C2 1024
#define C3 1024
#define NUM_GRAPHS 16
#define H3 512
#define NUM_CLASSES 2

// ---------------- scratch (device globals) ------------------------------------
__device__ __half d_h16[N_NODES * C1];           // GEMM output / y16 buffer
__device__ __half d_a16[N_NODES * C1];           // fp16 activations
__device__ __half d_wt16[C1 * C1];               // W^T fp16 [Nn, Kpad]
__device__ float  d_dinv[N_NODES];
__device__ int    d_cnt[N_NODES];
__device__ int    d_rowptr[N_NODES + 1];
__device__ int    d_wofs[N_NODES];
__device__ int    d_colidx[N_EDGES];
__device__ float  d_eval[N_EDGES];
__device__ float  d_pool[NUM_GRAPHS * C3];
__device__ float  d_gcnt[NUM_GRAPHS];
__device__ float  d_m1[NUM_GRAPHS * 1024];
__device__ float  d_m2[NUM_GRAPHS * 1024];
__device__ float  d_m3[NUM_GRAPHS * H3];

// ---------------- helpers -------------------------------------------------------
__device__ __forceinline__ uint32_t smem_u32(const void* p) {
    uint32_t a;
    asm("{ .reg .u64 t; cvta.to.shared.u64 t, %1; cvt.u32.u64 %0, t; }"
        : "=r"(a) : "l"(p));
    return a;
}
__device__ __forceinline__ void cp16(uint32_t dst, const void* src, bool pred) {
    int sz = pred ? 16 : 0;
    asm volatile("cp.async.cg.shared.global [%0], [%1], 16, %2;"
                 :: "r"(dst), "l"(src), "r"(sz) : "memory");
}
#define CP_COMMIT() asm volatile("cp.async.commit_group;" ::: "memory")
#define CP_WAIT2()  asm volatile("cp.async.wait_group 2;" ::: "memory")

__device__ __forceinline__ void ldsm4(uint32_t (&r)[4], uint32_t a) {
    asm volatile("ldmatrix.sync.aligned.m8n8.x4.shared.b16 {%0,%1,%2,%3}, [%4];"
        : "=r"(r[0]), "=r"(r[1]), "=r"(r[2]), "=r"(r[3]) : "r"(a));
}
__device__ __forceinline__ void mma16816(float (&d)[4], const uint32_t (&a)[4],
                                         const uint32_t* b) {
    asm volatile("mma.sync.aligned.m16n8k16.row.col.f32.f16.f16.f32 "
        "{%0,%1,%2,%3}, {%4,%5,%6,%7}, {%8,%9}, {%0,%1,%2,%3};"
        : "+f"(d[0]), "+f"(d[1]), "+f"(d[2]), "+f"(d[3])
        : "r"(a[0]), "r"(a[1]), "r"(a[2]), "r"(a[3]), "r"(b[0]), "r"(b[1]));
}

// ---------------- setup kernels -------------------------------------------------
__global__ void init_kernel() {
    int i = blockIdx.x * blockDim.x + threadIdx.x;
    int total = N_NODES + NUM_GRAPHS * C3 + NUM_GRAPHS;
    for (; i < total; i += gridDim.x * blockDim.x) {
        if (i < N_NODES) d_cnt[i] = 0;
        else if (i < N_NODES + NUM_GRAPHS * C3) d_pool[i - N_NODES] = 0.0f;
        else d_gcnt[i - N_NODES - NUM_GRAPHS * C3] = 0.0f;
    }
}
__global__ void count_kernel(const int* __restrict__ ei,
                             const int* __restrict__ batch) {
    int idx = blockIdx.x * blockDim.x + threadIdx.x;
    if (idx < N_EDGES) atomicAdd(&d_cnt[ei[N_EDGES + idx]], 1);
    if (idx < N_NODES) atomicAdd(&d_gcnt[batch[idx]], 1.0f);
}
// fused: exclusive scan of counts + dinv (warp-shuffle scan, 2 barriers)
__global__ void scan_kernel() {
    __shared__ int wsum[32];
    const int CH = (N_NODES + 1023) / 1024;  // 10
    int tid = threadIdx.x, lane = tid & 31, wid = tid >> 5;
    int base = tid * CH, s = 0;
    for (int k = 0; k < CH; k++) { int i = base + k; if (i < N_NODES) s += d_cnt[i]; }
    int v = s;
    #pragma unroll
    for (int off = 1; off < 32; off <<= 1) {
        int t = __shfl_up_sync(0xffffffffu, v, off);
        if (lane >= off) v += t;
    }
    if (lane == 31) wsum[wid] = v;
    __syncthreads();
    if (wid == 0) {
        int w = wsum[lane];
        #pragma unroll
        for (int off = 1; off < 32; off <<= 1) {
            int t = __shfl_up_sync(0xffffffffu, w, off);
            if (lane >= off) w += t;
        }
        wsum[lane] = w;
    }
    __syncthreads();
    int run = (v - s) + (wid > 0 ? wsum[wid - 1] : 0);  // exclusive prefix
    for (int k = 0; k < CH; k++) {
        int i = base + k;
        if (i < N_NODES) {
            d_rowptr[i] = run; d_wofs[i] = run; run += d_cnt[i];
            d_dinv[i] = rsqrtf((float)(d_cnt[i] + 1));
        }
    }
    if (tid == 1023) d_rowptr[N_NODES] = run;
}
__global__ void fill_kernel(const int* __restrict__ ei) {
    int e = blockIdx.x * blockDim.x + threadIdx.x;
    if (e < N_EDGES) {
        int src = ei[e], dst = ei[N_EDGES + e];
        int pos = atomicAdd(&d_wofs[dst], 1);
        d_colidx[pos] = src;
        d_eval[pos] = d_dinv[src] * d_dinv[dst];
    }
}
// embed + concat straight to fp16 (padded to K1PAD)
__global__ void embed_kernel(const int* __restrict__ tids,
                             const float* __restrict__ other,
                             const float* __restrict__ emb) {
    int i = blockIdx.x, c = threadIdx.x;  // c in [0, K1PAD)
    float v = 0.0f;
    if (c < EMB_DIM) v = emb[tids[i] * EMB_DIM + c];
    else if (c < IN_GNN) v = other[i * (IN_CH - 1) + (c - EMB_DIM)];
    d_a16[i * K1PAD + c] = __float2half(v);
}

// W [Kin, Nn] fp32 -> Wt fp16 [Nn, Kpad]
__global__ void tconv_w_kernel(const float* __restrict__ W, int Kin, int Kpad, int Nn) {
    __shared__ float t[32][33];
    int k0 = blockIdx.x * 32, n0 = blockIdx.y * 32;
    int tx = threadIdx.x, ty = threadIdx.y;
    int k = k0 + ty, n = n0 + tx;
    t[ty][tx] = (k < Kin) ? W[(long)k * Nn + n] : 0.0f;
    __syncthreads();
    int nw = n0 + ty, kw = k0 + tx;
    d_wt16[(long)nw * Kpad + kw] = __float2half(t[tx][ty]);
}

// ---------------- mma.sync fp16 GEMM (128x128, BK=64, 3 stages) ----------------
// Optional fused bias+ReLU epilogue (bias != nullptr).
#define BM 128
#define BN 128
#define BK 64
#define TILE_BYTES (128 * 64 * 2)      // 16 KB per tile
#define STAGE_BYTES (2 * TILE_BYTES)   // 32 KB (A, B)
#define NSTAGE 3

__global__ __launch_bounds__(256) void mma_gemm_kernel(
    const __half* __restrict__ A, const __half* __restrict__ B,
    __half* __restrict__ C16, const float* __restrict__ bias,
    int M, int Nn, int Kp) {
    extern __shared__ char smem[];
    uint32_t sbase = smem_u32(smem);
    int tid = threadIdx.x;
    int row0 = blockIdx.y * BM, col0 = blockIdx.x * BN;
    int nkt = Kp / BK;

    int w = tid >> 5, lane = tid & 31;
    int wm = (w & 3) * 32;   // 4 warps along M
    int wn = (w >> 2) * 64;  // 2 warps along N
    int q = lane >> 3, rr = lane & 7;

    float acc[2][8][4] = {};

    auto issue_stage = [&](int kt, int slot) {
        int k0 = kt * BK;
        #pragma unroll
        for (int i = 0; i < 8; i++) {
            int idx = tid + i * 256;
            int t = idx >> 10;           // 0 = A, 1 = B
            int r = (idx >> 3) & 127;
            int c = idx & 7;
            int grow = ((t == 0) ? row0 : col0) + r;
            bool ok = (t == 1) || (grow < M);
            const __half* s = (t == 0) ? A : B;
            const char* gp = (const char*)(s + (size_t)(ok ? grow : 0) * Kp + k0) + c * 16;
            uint32_t so = sbase + slot * STAGE_BYTES + t * TILE_BYTES
                        + r * 128 + ((c ^ (r & 7)) << 4);
            cp16(so, gp, ok);
        }
        CP_COMMIT();
    };

    #pragma unroll
    for (int s = 0; s < NSTAGE; s++) {
        if (s < nkt) issue_stage(s, s); else CP_COMMIT();
    }

    int st = 0;
    for (int kt = 0; kt < nkt; kt++) {
        CP_WAIT2();
        __syncthreads();
        uint32_t abase = sbase + st * STAGE_BYTES;
        uint32_t bbase = abase + TILE_BYTES;
        #pragma unroll
        for (int ks = 0; ks < 4; ks++) {
            uint32_t ah[2][4];
            #pragma unroll
            for (int mf = 0; mf < 2; mf++) {
                int row = wm + mf * 16 + (q & 1) * 8 + rr;
                int c = 2 * ks + (q >> 1);
                uint32_t off = row * 128 + ((c ^ (row & 7)) << 4);
                ldsm4(ah[mf], abase + off);
            }
            uint32_t bfr[8][2];
            #pragma unroll
            for (int nf2 = 0; nf2 < 4; nf2++) {
                int n = wn + nf2 * 16 + (q >> 1) * 8 + rr;
                int c = 2 * ks + (q & 1);
                uint32_t off = n * 128 + ((c ^ (n & 7)) << 4);
                uint32_t t0[4];
                ldsm4(t0, bbase + off);
                bfr[2*nf2][0] = t0[0]; bfr[2*nf2][1] = t0[1];
                bfr[2*nf2+1][0] = t0[2]; bfr[2*nf2+1][1] = t0[3];
            }
            #pragma unroll
            for (int mf = 0; mf < 2; mf++)
                #pragma unroll
                for (int nf = 0; nf < 8; nf++)
                    mma16816(acc[mf][nf], ah[mf], bfr[nf]);
        }
        __syncthreads();
        if (kt + NSTAGE < nkt) issue_stage(kt + NSTAGE, st);
        else CP_COMMIT();
        st = (st == NSTAGE - 1) ? 0 : st + 1;
    }

    // epilogue: fp16 output, optional fused bias+ReLU
    #pragma unroll
    for (int mf = 0; mf < 2; mf++) {
        int r0 = row0 + wm + mf * 16 + (lane >> 2);
        #pragma unroll
        for (int nf = 0; nf < 8; nf++) {
            int cc = col0 + wn + nf * 8 + (lane & 3) * 2;
            float v0 = acc[mf][nf][0], v1 = acc[mf][nf][1];
            float v2 = acc[mf][nf][2], v3 = acc[mf][nf][3];
            if (bias) {
                float bx = __ldg(bias + cc), by = __ldg(bias + cc + 1);
                v0 = fmaxf(v0 + bx, 0.0f); v1 = fmaxf(v1 + by, 0.0f);
                v2 = fmaxf(v2 + bx, 0.0f); v3 = fmaxf(v3 + by, 0.0f);
            }
            if (r0 < M)
                *(__half2*)(C16 + (size_t)r0 * Nn + cc) = __floats2half2_rn(v0, v1);
            if (r0 + 8 < M)
                *(__half2*)(C16 + (size_t)(r0 + 8) * Nn + cc) = __floats2half2_rn(v2, v3);
        }
    }
}

// ------ common 4-channel gather body --------------------------------------------
__device__ __forceinline__ void acc4(float (&a)[4], float wv, uint2 v) {
    __half2 lo = *(__half2*)&v.x, hi = *(__half2*)&v.y;
    float2 f0 = __half22float2(lo), f1 = __half22float2(hi);
    a[0] = fmaf(wv, f0.x, a[0]); a[1] = fmaf(wv, f0.y, a[1]);
    a[2] = fmaf(wv, f1.x, a[2]); a[3] = fmaf(wv, f1.y, a[3]);
}
__device__ __forceinline__ void gather_row(float (&a)[4], const uint2* h4,
                                           int i, int nc4, int c4) {
    float di = d_dinv[i];
    acc4(a, di * di, h4[(size_t)i * nc4 + c4]);
    int e0 = d_rowptr[i], e1 = d_rowptr[i + 1];
    int e = e0;
    for (; e + 4 <= e1; e += 4) {
        int   i0 = d_colidx[e],     i1 = d_colidx[e + 1];
        int   i2 = d_colidx[e + 2], i3 = d_colidx[e + 3];
        float w0e = d_eval[e],      w1e = d_eval[e + 1];
        float w2e = d_eval[e + 2],  w3e = d_eval[e + 3];
        uint2 v0 = h4[(size_t)i0 * nc4 + c4];
        uint2 v1 = h4[(size_t)i1 * nc4 + c4];
        uint2 v2 = h4[(size_t)i2 * nc4 + c4];
        uint2 v3 = h4[(size_t)i3 * nc4 + c4];
        acc4(a, w0e, v0); acc4(a, w1e, v1); acc4(a, w2e, v2); acc4(a, w3e, v3);
    }
    for (; e < e1; e++)
        acc4(a, d_eval[e], h4[(size_t)d_colidx[e] * nc4 + c4]);
}

// ------ SpMM + bias + ReLU (layers 2, 3) ----------------------------------------
__global__ void spmm_relu_kernel(const __half* __restrict__ h16,
                                 const float* __restrict__ bias,
                                 __half* __restrict__ out16, int Cch) {
    int i = blockIdx.x;
    int c4 = blockIdx.y * blockDim.x + threadIdx.x;
    int nc4 = Cch >> 2;
    if (c4 >= nc4) return;
    float a[4] = {0.f, 0.f, 0.f, 0.f};
    gather_row(a, (const uint2*)h16, i, nc4, c4);
    const float4 bv = *(const float4*)(bias + 4 * c4);
    a[0] += bv.x; a[1] += bv.y; a[2] += bv.z; a[3] += bv.w;
    #pragma unroll
    for (int t = 0; t < 4; t++) a[t] = a[t] > 0.0f ? a[t] : 0.0f;
    uint2 o;
    *(__half2*)&o.x = __floats2half2_rn(a[0], a[1]);
    *(__half2*)&o.y = __floats2half2_rn(a[2], a[3]);
    ((uint2*)out16)[(size_t)i * nc4 + c4] = o;
}

// ------ plain aggregate SpMM for narrow layer-1 input (no bias/relu) ------------
#define NPB 5
__global__ void spmm_agg_kernel(const __half* __restrict__ x16,
                                __half* __restrict__ y16) {
    const int nc4 = K1PAD >> 2;  // 48
    int c4 = threadIdx.x;
    int i = blockIdx.x * NPB + threadIdx.y;
    if (c4 >= nc4 || i >= N_NODES) return;
    float a[4] = {0.f, 0.f, 0.f, 0.f};
    gather_row(a, (const uint2*)x16, i, nc4, c4);
    uint2 o;
    *(__half2*)&o.x = __floats2half2_rn(a[0], a[1]);
    *(__half2*)&o.y = __floats2half2_rn(a[2], a[3]);
    ((uint2*)y16)[(size_t)i * nc4 + c4] = o;
}

// ---------------- pooling (reads fp16 activations) -----------------------------
#define POOL_CHUNK 32
__global__ void pool_kernel(const __half* __restrict__ h16,
                            const int* __restrict__ batch) {
    int c = blockIdx.y * blockDim.x + threadIdx.x;   // channel
    int i0 = blockIdx.x * POOL_CHUNK;
    int iend = min(i0 + POOL_CHUNK, N_NODES);
    if (i0 >= N_NODES) return;
    float acc = 0.0f;
    int cur = batch[i0];
    for (int i = i0; i < iend; i++) {
        int b = batch[i];
        if (b != cur) { atomicAdd(&d_pool[cur * C3 + c], acc); acc = 0.0f; cur = b; }
        acc += __half2float(h16[(size_t)i * C3 + c]);
    }
    atomicAdd(&d_pool[cur * C3 + c], acc);
}

// ---------------- small MLP (optional mean-divide on input) ---------------------
__global__ void mlp_kernel(const float* __restrict__ in,
                           const float* __restrict__ W,
                           const float* __restrict__ bias,
                           float* __restrict__ out,
                           int K, int Mo, int do_relu, int do_mean) {
    __shared__ float sin[1024];
    int row = blockIdx.y;
    float scale = 1.0f;
    if (do_mean) scale = 1.0f / fmaxf(d_gcnt[row], 1.0f);
    for (int k = threadIdx.x; k < K; k += blockDim.x)
        sin[k] = in[row * K + k] * scale;
    __syncthreads();
    int col = blockIdx.x * blockDim.x + threadIdx.x;
    if (col < Mo) {
        float acc = bias[col];
        for (int k = 0; k < K; k++) acc = fmaf(sin[k], W[k * Mo + col], acc);
        if (do_relu) acc = acc > 0.0f ? acc : 0.0f;
        out[row * Mo + col] = acc;
    }
}

// ---------------- launch --------------------------------------------------------
extern "C" void kernel_launch(void* const* d_in, const int* in_sizes, int n_in,
                              void* d_out, int out_size) {
    const int*   type_ids = (const int*)  d_in[0];
    const float* other    = (const float*)d_in[1];
    const int*   eidx     = (const int*)  d_in[2];
    const int*   batch    = (const int*)  d_in[3];
    const float* emb      = (const float*)d_in[4];
    const float* W1 = (const float*)d_in[5];  const float* b1 = (const float*)d_in[6];
    const float* W2 = (const float*)d_in[7];  const float* b2 = (const float*)d_in[8];
    const float* W3 = (const float*)d_in[9];  const float* b3 = (const float*)d_in[10];
    const float* h1w = (const float*)d_in[11]; const float* h1b = (const float*)d_in[12];
    const float* h2w = (const float*)d_in[13]; const float* h2b = (const float*)d_in[14];
    const float* h3w = (const float*)d_in[15]; const float* h3b = (const float*)d_in[16];
    const float* ow  = (const float*)d_in[17]; const float* ob  = (const float*)d_in[18];
    float* out = (float*)d_out;

    float* pool_p; cudaGetSymbolAddress((void**)&pool_p, d_pool);
    float* m1_p;   cudaGetSymbolAddress((void**)&m1_p,  d_m1);
    float* m2_p;   cudaGetSymbolAddress((void**)&m2_p,  d_m2);
    float* m3_p;   cudaGetSymbolAddress((void**)&m3_p,  d_m3);
    __half* h16_p; cudaGetSymbolAddress((void**)&h16_p, d_h16);
    __half* a16_p; cudaGetSymbolAddress((void**)&a16_p, d_a16);
    __half* wt_p;  cudaGetSymbolAddress((void**)&wt_p,  d_wt16);

    static int smem_set = 0;
    if (!smem_set) {
        cudaFuncSetAttribute(mma_gemm_kernel,
                             cudaFuncAttributeMaxDynamicSharedMemorySize,
                             NSTAGE * STAGE_BYTES);
        smem_set = 1;
    }

    // graph structure
    init_kernel<<<128, 256>>>();
    count_kernel<<<(N_EDGES + 255) / 256, 256>>>(eidx, batch);
    scan_kernel<<<1, 1024>>>();
    fill_kernel<<<(N_EDGES + 255) / 256, 256>>>(eidx);
    embed_kernel<<<N_NODES, K1PAD>>>(type_ids, other, emb);

    const int MT = (N_NODES + BM - 1) / BM;  // 79

    // --- layer 1 (reordered): y = agg(x) [N,192]; a = relu(y@W1t + b1) ----------
    {
        dim3 ag((N_NODES + NPB - 1) / NPB);
        spmm_agg_kernel<<<ag, dim3(K1PAD / 4, NPB)>>>(a16_p, h16_p);
        dim3 tg(K1PAD / 32, C1 / 32);
        tconv_w_kernel<<<tg, dim3(32, 32)>>>(W1, IN_GNN, K1PAD, C1);
        dim3 grid(C1 / BN, MT);
        mma_gemm_kernel<<<grid, 256, NSTAGE * STAGE_BYTES>>>(h16_p, wt_p, a16_p, b1,
                                                             N_NODES, C1, K1PAD);
    }
    // --- layer 2: h = a@W2t; a = relu(agg(h) + b2) -------------------------------
    {
        dim3 tg(C1 / 32, C2 / 32);
        tconv_w_kernel<<<tg, dim3(32, 32)>>>(W2, C1, C1, C2);
        dim3 grid(C2 / BN, MT);
        mma_gemm_kernel<<<grid, 256, NSTAGE * STAGE_BYTES>>>(a16_p, wt_p, h16_p,
                                                             nullptr, N_NODES, C2, C1);
        dim3 sg(N_NODES, (C2 / 4) / 256);
        spmm_relu_kernel<<<sg, 256>>>(h16_p, b2, a16_p, C2);
    }
    // --- layer 3: h = a@W3t; a = relu(agg(h) + b3) -------------------------------
    {
        dim3 tg(C2 / 32, C3 / 32);
        tconv_w_kernel<<<tg, dim3(32, 32)>>>(W3, C2, C2, C3);
        dim3 grid(C3 / BN, MT);
        mma_gemm_kernel<<<grid, 256, NSTAGE * STAGE_BYTES>>>(a16_p, wt_p, h16_p,
                                                             nullptr, N_NODES, C3, C2);
        dim3 sg(N_NODES, (C3 / 4) / 256);
        spmm_relu_kernel<<<sg, 256>>>(h16_p, b3, a16_p, C3);
    }

    // pool + head (mean folded into first MLP layer)
    {
        dim3 grid((N_NODES + POOL_CHUNK - 1) / POOL_CHUNK, C3 / 256);
        pool_kernel<<<grid, 256>>>(a16_p, batch);
        dim3 g1(1024 / 256, NUM_GRAPHS);
        mlp_kernel<<<g1, 256>>>(pool_p, h1w, h1b, m1_p, 1024, 1024, 1, 1);
        mlp_kernel<<<g1, 256>>>(m1_p, h2w, h2b, m2_p, 1024, 1024, 1, 0);
        dim3 g3(H3 / 256, NUM_GRAPHS);
        mlp_kernel<<<g3, 256>>>(m2_p, h3w, h3b, m3_p, 1024, H3, 1, 0);
        dim3 g4(1, NUM_GRAPHS);
        mlp_kernel<<<g4, 256>>>(m3_p, ow, ob, out, H3, NUM_CLASSES, 0, 0);
    }
}

// round 15
// speedup vs baseline: 1.1743x; 1.0234x over previous
#include <cuda_runtime.h>
#include <cuda_fp16.h>
#include <math.h>
#include <stdint.h>

#define N_NODES 10000
#define N_EDGES 80000
#define EMB_DIM 128
#define IN_CH 64
#define IN_GNN 191
#define K1PAD 192
#define C1 2048
#define C2 1024
#define C3 1024
#define NUM_GRAPHS 16
#define H3 512
#define NUM_CLASSES 2

// ---------------- scratch (device globals) ------------------------------------
__device__ __half d_h16[N_NODES * C1];           // GEMM output / y16 buffer
__device__ __half d_a16[N_NODES * C1];           // fp16 activations
__device__ __half d_wt1[C1 * K1PAD];             // W1^T fp16 [2048, 192]
__device__ __half d_wt2[C2 * C1];                // W2^T fp16 [1024, 2048]
__device__ __half d_wt3[C3 * C2];                // W3^T fp16 [1024, 1024]
__device__ float  d_dinv[N_NODES];
__device__ int    d_cnt[N_NODES];
__device__ int    d_rowptr[N_NODES + 1];
__device__ int    d_wofs[N_NODES];
__device__ int    d_colidx[N_EDGES];
__device__ float  d_eval[N_EDGES];
__device__ float  d_pool[NUM_GRAPHS * C3];
__device__ float  d_gcnt[NUM_GRAPHS];
__device__ float  d_m1[NUM_GRAPHS * 1024];
__device__ float  d_m2[NUM_GRAPHS * 1024];
__device__ float  d_m3[NUM_GRAPHS * H3];

// ---------------- helpers -------------------------------------------------------
__device__ __forceinline__ uint32_t smem_u32(const void* p) {
    uint32_t a;
    asm("{ .reg .u64 t; cvta.to.shared.u64 t, %1; cvt.u32.u64 %0, t; }"
        : "=r"(a) : "l"(p));
    return a;
}
__device__ __forceinline__ void cp16(uint32_t dst, const void* src, bool pred) {
    int sz = pred ? 16 : 0;
    asm volatile("cp.async.cg.shared.global [%0], [%1], 16, %2;"
                 :: "r"(dst), "l"(src), "r"(sz) : "memory");
}
#define CP_COMMIT() asm volatile("cp.async.commit_group;" ::: "memory")
#define CP_WAIT2()  asm volatile("cp.async.wait_group 2;" ::: "memory")

__device__ __forceinline__ void ldsm4(uint32_t (&r)[4], uint32_t a) {
    asm volatile("ldmatrix.sync.aligned.m8n8.x4.shared.b16 {%0,%1,%2,%3}, [%4];"
        : "=r"(r[0]), "=r"(r[1]), "=r"(r[2]), "=r"(r[3]) : "r"(a));
}
__device__ __forceinline__ void mma16816(float (&d)[4], const uint32_t (&a)[4],
                                         const uint32_t* b) {
    asm volatile("mma.sync.aligned.m16n8k16.row.col.f32.f16.f16.f32 "
        "{%0,%1,%2,%3}, {%4,%5,%6,%7}, {%8,%9}, {%0,%1,%2,%3};"
        : "+f"(d[0]), "+f"(d[1]), "+f"(d[2]), "+f"(d[3])
        : "r"(a[0]), "r"(a[1]), "r"(a[2]), "r"(a[3]), "r"(b[0]), "r"(b[1]));
}

// ---------------- setup kernels -------------------------------------------------
__global__ void init_kernel() {
    int i = blockIdx.x * blockDim.x + threadIdx.x;
    int total = N_NODES + NUM_GRAPHS * C3 + NUM_GRAPHS;
    for (; i < total; i += gridDim.x * blockDim.x) {
        if (i < N_NODES) d_cnt[i] = 0;
        else if (i < N_NODES + NUM_GRAPHS * C3) d_pool[i - N_NODES] = 0.0f;
        else d_gcnt[i - N_NODES - NUM_GRAPHS * C3] = 0.0f;
    }
}
__global__ void count_kernel(const int* __restrict__ ei,
                             const int* __restrict__ batch) {
    int idx = blockIdx.x * blockDim.x + threadIdx.x;
    if (idx < N_EDGES) atomicAdd(&d_cnt[ei[N_EDGES + idx]], 1);
    if (idx < N_NODES) atomicAdd(&d_gcnt[batch[idx]], 1.0f);
}
// fused: exclusive scan of counts + dinv (warp-shuffle scan, 2 barriers)
__global__ void scan_kernel() {
    __shared__ int wsum[32];
    const int CH = (N_NODES + 1023) / 1024;  // 10
    int tid = threadIdx.x, lane = tid & 31, wid = tid >> 5;
    int base = tid * CH, s = 0;
    for (int k = 0; k < CH; k++) { int i = base + k; if (i < N_NODES) s += d_cnt[i]; }
    int v = s;
    #pragma unroll
    for (int off = 1; off < 32; off <<= 1) {
        int t = __shfl_up_sync(0xffffffffu, v, off);
        if (lane >= off) v += t;
    }
    if (lane == 31) wsum[wid] = v;
    __syncthreads();
    if (wid == 0) {
        int w = wsum[lane];
        #pragma unroll
        for (int off = 1; off < 32; off <<= 1) {
            int t = __shfl_up_sync(0xffffffffu, w, off);
            if (lane >= off) w += t;
        }
        wsum[lane] = w;
    }
    __syncthreads();
    int run = (v - s) + (wid > 0 ? wsum[wid - 1] : 0);  // exclusive prefix
    for (int k = 0; k < CH; k++) {
        int i = base + k;
        if (i < N_NODES) {
            d_rowptr[i] = run; d_wofs[i] = run; run += d_cnt[i];
            d_dinv[i] = rsqrtf((float)(d_cnt[i] + 1));
        }
    }
    if (tid == 1023) d_rowptr[N_NODES] = run;
}
__global__ void fill_kernel(const int* __restrict__ ei) {
    int e = blockIdx.x * blockDim.x + threadIdx.x;
    if (e < N_EDGES) {
        int src = ei[e], dst = ei[N_EDGES + e];
        int pos = atomicAdd(&d_wofs[dst], 1);
        d_colidx[pos] = src;
        d_eval[pos] = d_dinv[src] * d_dinv[dst];
    }
}
// embed + concat straight to fp16 (padded to K1PAD)
__global__ void embed_kernel(const int* __restrict__ tids,
                             const float* __restrict__ other,
                             const float* __restrict__ emb) {
    int i = blockIdx.x, c = threadIdx.x;  // c in [0, K1PAD)
    float v = 0.0f;
    if (c < EMB_DIM) v = emb[tids[i] * EMB_DIM + c];
    else if (c < IN_GNN) v = other[i * (IN_CH - 1) + (c - EMB_DIM)];
    d_a16[i * K1PAD + c] = __float2half(v);
}

// W [Kin, Nn] fp32 -> Wt fp16 [Nn, Kpad] (dst as parameter)
__global__ void tconv_w_kernel(const float* __restrict__ W, __half* __restrict__ dst,
                               int Kin, int Kpad, int Nn) {
    __shared__ float t[32][33];
    int k0 = blockIdx.x * 32, n0 = blockIdx.y * 32;
    int tx = threadIdx.x, ty = threadIdx.y;
    int k = k0 + ty, n = n0 + tx;
    t[ty][tx] = (k < Kin) ? W[(long)k * Nn + n] : 0.0f;
    __syncthreads();
    int nw = n0 + ty, kw = k0 + tx;
    dst[(long)nw * Kpad + kw] = __float2half(t[tx][ty]);
}

// ---------------- mma.sync fp16 GEMM (128x128, BK=64, 3 stages) ----------------
// Optional fused bias+ReLU epilogue (bias != nullptr).
#define BM 128
#define BN 128
#define BK 64
#define TILE_BYTES (128 * 64 * 2)      // 16 KB per tile
#define STAGE_BYTES (2 * TILE_BYTES)   // 32 KB (A, B)
#define NSTAGE 3

__global__ __launch_bounds__(256) void mma_gemm_kernel(
    const __half* __restrict__ A, const __half* __restrict__ B,
    __half* __restrict__ C16, const float* __restrict__ bias,
    int M, int Nn, int Kp) {
    extern __shared__ char smem[];
    uint32_t sbase = smem_u32(smem);
    int tid = threadIdx.x;
    int row0 = blockIdx.y * BM, col0 = blockIdx.x * BN;
    int nkt = Kp / BK;

    int w = tid >> 5, lane = tid & 31;
    int wm = (w & 3) * 32;   // 4 warps along M
    int wn = (w >> 2) * 64;  // 2 warps along N
    int q = lane >> 3, rr = lane & 7;

    float acc[2][8][4] = {};

    auto issue_stage = [&](int kt, int slot) {
        int k0 = kt * BK;
        #pragma unroll
        for (int i = 0; i < 8; i++) {
            int idx = tid + i * 256;
            int t = idx >> 10;           // 0 = A, 1 = B
            int r = (idx >> 3) & 127;
            int c = idx & 7;
            int grow = ((t == 0) ? row0 : col0) + r;
            bool ok = (t == 1) || (grow < M);
            const __half* s = (t == 0) ? A : B;
            const char* gp = (const char*)(s + (size_t)(ok ? grow : 0) * Kp + k0) + c * 16;
            uint32_t so = sbase + slot * STAGE_BYTES + t * TILE_BYTES
                        + r * 128 + ((c ^ (r & 7)) << 4);
            cp16(so, gp, ok);
        }
        CP_COMMIT();
    };

    #pragma unroll
    for (int s = 0; s < NSTAGE; s++) {
        if (s < nkt) issue_stage(s, s); else CP_COMMIT();
    }

    int st = 0;
    for (int kt = 0; kt < nkt; kt++) {
        CP_WAIT2();
        __syncthreads();
        uint32_t abase = sbase + st * STAGE_BYTES;
        uint32_t bbase = abase + TILE_BYTES;
        #pragma unroll
        for (int ks = 0; ks < 4; ks++) {
            uint32_t ah[2][4];
            #pragma unroll
            for (int mf = 0; mf < 2; mf++) {
                int row = wm + mf * 16 + (q & 1) * 8 + rr;
                int c = 2 * ks + (q >> 1);
                uint32_t off = row * 128 + ((c ^ (row & 7)) << 4);
                ldsm4(ah[mf], abase + off);
            }
            uint32_t bfr[8][2];
            #pragma unroll
            for (int nf2 = 0; nf2 < 4; nf2++) {
                int n = wn + nf2 * 16 + (q >> 1) * 8 + rr;
                int c = 2 * ks + (q & 1);
                uint32_t off = n * 128 + ((c ^ (n & 7)) << 4);
                uint32_t t0[4];
                ldsm4(t0, bbase + off);
                bfr[2*nf2][0] = t0[0]; bfr[2*nf2][1] = t0[1];
                bfr[2*nf2+1][0] = t0[2]; bfr[2*nf2+1][1] = t0[3];
            }
            #pragma unroll
            for (int mf = 0; mf < 2; mf++)
                #pragma unroll
                for (int nf = 0; nf < 8; nf++)
                    mma16816(acc[mf][nf], ah[mf], bfr[nf]);
        }
        __syncthreads();
        if (kt + NSTAGE < nkt) issue_stage(kt + NSTAGE, st);
        else CP_COMMIT();
        st = (st == NSTAGE - 1) ? 0 : st + 1;
    }

    // epilogue: fp16 output, optional fused bias+ReLU
    #pragma unroll
    for (int mf = 0; mf < 2; mf++) {
        int r0 = row0 + wm + mf * 16 + (lane >> 2);
        #pragma unroll
        for (int nf = 0; nf < 8; nf++) {
            int cc = col0 + wn + nf * 8 + (lane & 3) * 2;
            float v0 = acc[mf][nf][0], v1 = acc[mf][nf][1];
            float v2 = acc[mf][nf][2], v3 = acc[mf][nf][3];
            if (bias) {
                float bx = __ldg(bias + cc), by = __ldg(bias + cc + 1);
                v0 = fmaxf(v0 + bx, 0.0f); v1 = fmaxf(v1 + by, 0.0f);
                v2 = fmaxf(v2 + bx, 0.0f); v3 = fmaxf(v3 + by, 0.0f);
            }
            if (r0 < M)
                *(__half2*)(C16 + (size_t)r0 * Nn + cc) = __floats2half2_rn(v0, v1);
            if (r0 + 8 < M)
                *(__half2*)(C16 + (size_t)(r0 + 8) * Nn + cc) = __floats2half2_rn(v2, v3);
        }
    }
}

// ------ common 4-channel gather body --------------------------------------------
__device__ __forceinline__ void acc4(float (&a)[4], float wv, uint2 v) {
    __half2 lo = *(__half2*)&v.x, hi = *(__half2*)&v.y;
    float2 f0 = __half22float2(lo), f1 = __half22float2(hi);
    a[0] = fmaf(wv, f0.x, a[0]); a[1] = fmaf(wv, f0.y, a[1]);
    a[2] = fmaf(wv, f1.x, a[2]); a[3] = fmaf(wv, f1.y, a[3]);
}
__device__ __forceinline__ void gather_row(float (&a)[4], const uint2* h4,
                                           int i, int nc4, int c4) {
    float di = d_dinv[i];
    acc4(a, di * di, h4[(size_t)i * nc4 + c4]);
    int e0 = d_rowptr[i], e1 = d_rowptr[i + 1];
    int e = e0;
    for (; e + 4 <= e1; e += 4) {
        int   i0 = d_colidx[e],     i1 = d_colidx[e + 1];
        int   i2 = d_colidx[e + 2], i3 = d_colidx[e + 3];
        float w0e = d_eval[e],      w1e = d_eval[e + 1];
        float w2e = d_eval[e + 2],  w3e = d_eval[e + 3];
        uint2 v0 = h4[(size_t)i0 * nc4 + c4];
        uint2 v1 = h4[(size_t)i1 * nc4 + c4];
        uint2 v2 = h4[(size_t)i2 * nc4 + c4];
        uint2 v3 = h4[(size_t)i3 * nc4 + c4];
        acc4(a, w0e, v0); acc4(a, w1e, v1); acc4(a, w2e, v2); acc4(a, w3e, v3);
    }
    for (; e < e1; e++)
        acc4(a, d_eval[e], h4[(size_t)d_colidx[e] * nc4 + c4]);
}

// ------ SpMM + bias + ReLU (layers 2, 3) ----------------------------------------
__global__ void spmm_relu_kernel(const __half* __restrict__ h16,
                                 const float* __restrict__ bias,
                                 __half* __restrict__ out16, int Cch) {
    int i = blockIdx.x;
    int c4 = blockIdx.y * blockDim.x + threadIdx.x;
    int nc4 = Cch >> 2;
    if (c4 >= nc4) return;
    float a[4] = {0.f, 0.f, 0.f, 0.f};
    gather_row(a, (const uint2*)h16, i, nc4, c4);
    const float4 bv = *(const float4*)(bias + 4 * c4);
    a[0] += bv.x; a[1] += bv.y; a[2] += bv.z; a[3] += bv.w;
    #pragma unroll
    for (int t = 0; t < 4; t++) a[t] = a[t] > 0.0f ? a[t] : 0.0f;
    uint2 o;
    *(__half2*)&o.x = __floats2half2_rn(a[0], a[1]);
    *(__half2*)&o.y = __floats2half2_rn(a[2], a[3]);
    ((uint2*)out16)[(size_t)i * nc4 + c4] = o;
}

// ------ plain aggregate SpMM for narrow layer-1 input (no bias/relu) ------------
#define NPB 5
__global__ void spmm_agg_kernel(const __half* __restrict__ x16,
                                __half* __restrict__ y16) {
    const int nc4 = K1PAD >> 2;  // 48
    int c4 = threadIdx.x;
    int i = blockIdx.x * NPB + threadIdx.y;
    if (c4 >= nc4 || i >= N_NODES) return;
    float a[4] = {0.f, 0.f, 0.f, 0.f};
    gather_row(a, (const uint2*)x16, i, nc4, c4);
    uint2 o;
    *(__half2*)&o.x = __floats2half2_rn(a[0], a[1]);
    *(__half2*)&o.y = __floats2half2_rn(a[2], a[3]);
    ((uint2*)y16)[(size_t)i * nc4 + c4] = o;
}

// ---------------- pooling (reads fp16 activations) -----------------------------
#define POOL_CHUNK 32
__global__ void pool_kernel(const __half* __restrict__ h16,
                            const int* __restrict__ batch) {
    int c = blockIdx.y * blockDim.x + threadIdx.x;   // channel
    int i0 = blockIdx.x * POOL_CHUNK;
    int iend = min(i0 + POOL_CHUNK, N_NODES);
    if (i0 >= N_NODES) return;
    float acc = 0.0f;
    int cur = batch[i0];
    for (int i = i0; i < iend; i++) {
        int b = batch[i];
        if (b != cur) { atomicAdd(&d_pool[cur * C3 + c], acc); acc = 0.0f; cur = b; }
        acc += __half2float(h16[(size_t)i * C3 + c]);
    }
    atomicAdd(&d_pool[cur * C3 + c], acc);
}

// ---------------- small MLP (optional mean-divide on input) ---------------------
__global__ void mlp_kernel(const float* __restrict__ in,
                           const float* __restrict__ W,
                           const float* __restrict__ bias,
                           float* __restrict__ out,
                           int K, int Mo, int do_relu, int do_mean) {
    __shared__ float sin[1024];
    int row = blockIdx.y;
    float scale = 1.0f;
    if (do_mean) scale = 1.0f / fmaxf(d_gcnt[row], 1.0f);
    for (int k = threadIdx.x; k < K; k += blockDim.x)
        sin[k] = in[row * K + k] * scale;
    __syncthreads();
    int col = blockIdx.x * blockDim.x + threadIdx.x;
    if (col < Mo) {
        float acc = bias[col];
        for (int k = 0; k < K; k++) acc = fmaf(sin[k], W[k * Mo + col], acc);
        if (do_relu) acc = acc > 0.0f ? acc : 0.0f;
        out[row * Mo + col] = acc;
    }
}

// ---------------- launch --------------------------------------------------------
extern "C" void kernel_launch(void* const* d_in, const int* in_sizes, int n_in,
                              void* d_out, int out_size) {
    const int*   type_ids = (const int*)  d_in[0];
    const float* other    = (const float*)d_in[1];
    const int*   eidx     = (const int*)  d_in[2];
    const int*   batch    = (const int*)  d_in[3];
    const float* emb      = (const float*)d_in[4];
    const float* W1 = (const float*)d_in[5];  const float* b1 = (const float*)d_in[6];
    const float* W2 = (const float*)d_in[7];  const float* b2 = (const float*)d_in[8];
    const float* W3 = (const float*)d_in[9];  const float* b3 = (const float*)d_in[10];
    const float* h1w = (const float*)d_in[11]; const float* h1b = (const float*)d_in[12];
    const float* h2w = (const float*)d_in[13]; const float* h2b = (const float*)d_in[14];
    const float* h3w = (const float*)d_in[15]; const float* h3b = (const float*)d_in[16];
    const float* ow  = (const float*)d_in[17]; const float* ob  = (const float*)d_in[18];
    float* out = (float*)d_out;

    float* pool_p; cudaGetSymbolAddress((void**)&pool_p, d_pool);
    float* m1_p;   cudaGetSymbolAddress((void**)&m1_p,  d_m1);
    float* m2_p;   cudaGetSymbolAddress((void**)&m2_p,  d_m2);
    float* m3_p;   cudaGetSymbolAddress((void**)&m3_p,  d_m3);
    __half* h16_p; cudaGetSymbolAddress((void**)&h16_p, d_h16);
    __half* a16_p; cudaGetSymbolAddress((void**)&a16_p, d_a16);
    __half* wt1_p; cudaGetSymbolAddress((void**)&wt1_p, d_wt1);
    __half* wt2_p; cudaGetSymbolAddress((void**)&wt2_p, d_wt2);
    __half* wt3_p; cudaGetSymbolAddress((void**)&wt3_p, d_wt3);

    static cudaStream_t s1 = nullptr, s2 = nullptr;
    static cudaEvent_t evRoot, evW1, evW2, evW3, evEmb;
    static int init_done = 0;
    if (!init_done) {
        cudaFuncSetAttribute(mma_gemm_kernel,
                             cudaFuncAttributeMaxDynamicSharedMemorySize,
                             NSTAGE * STAGE_BYTES);
        cudaStreamCreateWithFlags(&s1, cudaStreamNonBlocking);
        cudaStreamCreateWithFlags(&s2, cudaStreamNonBlocking);
        cudaEventCreateWithFlags(&evRoot, cudaEventDisableTiming);
        cudaEventCreateWithFlags(&evW1,   cudaEventDisableTiming);
        cudaEventCreateWithFlags(&evW2,   cudaEventDisableTiming);
        cudaEventCreateWithFlags(&evW3,   cudaEventDisableTiming);
        cudaEventCreateWithFlags(&evEmb,  cudaEventDisableTiming);
        init_done = 1;
    }

    // fork side streams from the main (captured) stream
    cudaEventRecord(evRoot, 0);
    cudaStreamWaitEvent(s1, evRoot, 0);
    cudaStreamWaitEvent(s2, evRoot, 0);

    // s1: weight transposes (independent of graph setup)
    {
        dim3 tg1(K1PAD / 32, C1 / 32);
        tconv_w_kernel<<<tg1, dim3(32, 32), 0, s1>>>(W1, wt1_p, IN_GNN, K1PAD, C1);
        cudaEventRecord(evW1, s1);
        dim3 tg2(C1 / 32, C2 / 32);
        tconv_w_kernel<<<tg2, dim3(32, 32), 0, s1>>>(W2, wt2_p, C1, C1, C2);
        cudaEventRecord(evW2, s1);
        dim3 tg3(C2 / 32, C3 / 32);
        tconv_w_kernel<<<tg3, dim3(32, 32), 0, s1>>>(W3, wt3_p, C2, C2, C3);
        cudaEventRecord(evW3, s1);
    }
    // s2: embed (independent of graph setup)
    embed_kernel<<<N_NODES, K1PAD, 0, s2>>>(type_ids, other, emb);
    cudaEventRecord(evEmb, s2);

    // main stream: graph structure
    init_kernel<<<128, 256>>>();
    count_kernel<<<(N_EDGES + 255) / 256, 256>>>(eidx, batch);
    scan_kernel<<<1, 1024>>>();
    fill_kernel<<<(N_EDGES + 255) / 256, 256>>>(eidx);

    const int MT = (N_NODES + BM - 1) / BM;  // 79

    // --- layer 1 (reordered): y = agg(x) [N,192]; a = relu(y@W1t + b1) ----------
    {
        cudaStreamWaitEvent(0, evEmb, 0);   // join s2
        dim3 ag((N_NODES + NPB - 1) / NPB);
        spmm_agg_kernel<<<ag, dim3(K1PAD / 4, NPB)>>>(a16_p, h16_p);
        cudaStreamWaitEvent(0, evW1, 0);
        dim3 grid(C1 / BN, MT);
        mma_gemm_kernel<<<grid, 256, NSTAGE * STAGE_BYTES>>>(h16_p, wt1_p, a16_p, b1,
                                                             N_NODES, C1, K1PAD);
    }
    // --- layer 2: h = a@W2t; a = relu(agg(h) + b2) -------------------------------
    {
        cudaStreamWaitEvent(0, evW2, 0);
        dim3 grid(C2 / BN, MT);
        mma_gemm_kernel<<<grid, 256, NSTAGE * STAGE_BYTES>>>(a16_p, wt2_p, h16_p,
                                                             nullptr, N_NODES, C2, C1);
        dim3 sg(N_NODES, (C2 / 4) / 256);
        spmm_relu_kernel<<<sg, 256>>>(h16_p, b2, a16_p, C2);
    }
    // --- layer 3: h = a@W3t; a = relu(agg(h) + b3) -------------------------------
    {
        cudaStreamWaitEvent(0, evW3, 0);    // join s1
        dim3 grid(C3 / BN, MT);
        mma_gemm_kernel<<<grid, 256, NSTAGE * STAGE_BYTES>>>(a16_p, wt3_p, h16_p,
                                                             nullptr, N_NODES, C3, C2);
        dim3 sg(N_NODES, (C3 / 4) / 256);
        spmm_relu_kernel<<<sg, 256>>>(h16_p, b3, a16_p, C3);
    }

    // pool + head (mean folded into first MLP layer)
    {
        dim3 grid((N_NODES + POOL_CHUNK - 1) / POOL_CHUNK, C3 / 256);
        pool_kernel<<<grid, 256>>>(a16_p, batch);
        dim3 g1(1024 / 256, NUM_GRAPHS);
        mlp_kernel<<<g1, 256>>>(pool_p, h1w, h1b, m1_p, 1024, 1024, 1, 1);
        mlp_kernel<<<g1, 256>>>(m1_p, h2w, h2b, m2_p, 1024, 1024, 1, 0);
        dim3 g3(H3 / 256, NUM_GRAPHS);
        mlp_kernel<<<g3, 256>>>(m2_p, h3w, h3b, m3_p, 1024, H3, 1, 0);
        dim3 g4(1, NUM_GRAPHS);
        mlp_kernel<<<g4, 256>>>(m3_p, ow, ob, out, H3, NUM_CLASSES, 0, 0);
    }
}